// round 4
// baseline (speedup 1.0000x reference)
#include <cuda_runtime.h>
#include <math_constants.h>

#define NPIX 4096
#define NB   8
#define INC  19
#define OUTC 64

// Folded weights / per-batch stats (device-global scratch: allowed)
__device__ float g_wA[INC];
__device__ float g_cA;
__device__ float g_u[OUTC];
__device__ float g_w0[OUTC];
__device__ float g_dmin[NB];
__device__ float g_dmax[NB];

// ---------------------------------------------------------------------------
// K0: fold weights.  wA = Wq^T Wk ; cA = bq . Wk ; u = Wo Wv ; w0 = Wo bv + bo
// One block, 64 threads.
// ---------------------------------------------------------------------------
__global__ void setup_kernel(const float* __restrict__ Wq,
                             const float* __restrict__ bq,
                             const float* __restrict__ Wk,
                             const float* __restrict__ Wv,
                             const float* __restrict__ bv,
                             const float* __restrict__ Wo,
                             const float* __restrict__ bo) {
    int t = threadIdx.x;  // 0..63
    if (t < INC) {
        float s = 0.f;
        #pragma unroll
        for (int c = 0; c < OUTC; c++) s = fmaf(Wk[c], Wq[c * INC + t], s);
        g_wA[t] = s;
    }
    if (t == 63) {
        float s = 0.f;
        #pragma unroll
        for (int c = 0; c < OUTC; c++) s = fmaf(Wk[c], bq[c], s);
        g_cA = s;
    }
    float su = 0.f, sw = 0.f;
    #pragma unroll
    for (int c = 0; c < OUTC; c++) {
        float w = Wo[t * OUTC + c];
        su = fmaf(w, Wv[c], su);
        sw = fmaf(w, bv[c], sw);
    }
    g_u[t]  = su;
    g_w0[t] = sw + bo[t];
}

// ---------------------------------------------------------------------------
// K1: per-batch min/max of d (softmax stabilization).  8 blocks x 256 thr.
// ---------------------------------------------------------------------------
__global__ void minmax_kernel(const float* __restrict__ d) {
    __shared__ float smn[8], smx[8];
    int b = blockIdx.x;
    const float* dp = d + b * NPIX;
    float mn =  CUDART_INF_F, mx = -CUDART_INF_F;
    for (int i = threadIdx.x; i < NPIX; i += 256) {
        float v = dp[i];
        mn = fminf(mn, v);
        mx = fmaxf(mx, v);
    }
    #pragma unroll
    for (int o = 16; o; o >>= 1) {
        mn = fminf(mn, __shfl_xor_sync(0xFFFFFFFFu, mn, o));
        mx = fmaxf(mx, __shfl_xor_sync(0xFFFFFFFFu, mx, o));
    }
    int w = threadIdx.x >> 5;
    if ((threadIdx.x & 31) == 0) { smn[w] = mn; smx[w] = mx; }
    __syncthreads();
    if (threadIdx.x == 0) {
        float a = smn[0], bb = smx[0];
        #pragma unroll
        for (int k = 1; k < 8; k++) { a = fminf(a, smn[k]); bb = fmaxf(bb, smx[k]); }
        g_dmin[b] = a;
        g_dmax[b] = bb;
    }
}

__device__ __forceinline__ float ex2(float x) {
    float r;
    asm("ex2.approx.ftz.f32 %0, %1;" : "=f"(r) : "f"(x));
    return r;
}

// ---------------------------------------------------------------------------
// K2: main.  grid (NPIX/128, NB), 128 threads.  Each thread owns one pixel j:
//   A_j = wA . seg[b,:,j] + cA
//   S_j = sum_i d_i e^{A_j d_i} / sum_i e^{A_j d_i}   (d in smem, max-shifted)
//   out[b,o,j] = u[o]*S_j + w0[o]
// ---------------------------------------------------------------------------
__global__ void __launch_bounds__(128, 8)
attn_kernel(const float* __restrict__ seg,
            const float* __restrict__ d,
            float* __restrict__ out) {
    __shared__ float ds[NPIX];
    __shared__ float su[OUTC], sw0[OUTC];

    const int b   = blockIdx.y;
    const int tid = threadIdx.x;
    const int j   = blockIdx.x * 128 + tid;

    // stage d[b,:] into smem (float4)
    const float4* dp4 = reinterpret_cast<const float4*>(d + b * NPIX);
    float4* ds4 = reinterpret_cast<float4*>(ds);
    #pragma unroll
    for (int i = tid; i < NPIX / 4; i += 128) ds4[i] = dp4[i];
    if (tid < OUTC) { su[tid] = g_u[tid]; sw0[tid] = g_w0[tid]; }
    __syncthreads();

    // A_j
    float a = g_cA;
    const float* segp = seg + (size_t)b * INC * NPIX + j;
    #pragma unroll
    for (int ic = 0; ic < INC; ic++)
        a = fmaf(g_wA[ic], segp[ic * NPIX], a);

    const float LOG2E = 1.4426950408889634f;
    float a2 = a * LOG2E;
    float m2 = (a2 > 0.f) ? a2 * g_dmax[b] : a2 * g_dmin[b];

    float num0 = 0.f, num1 = 0.f, num2 = 0.f, num3 = 0.f;
    float den0 = 0.f, den1 = 0.f, den2 = 0.f, den3 = 0.f;

    const float4* dv4 = reinterpret_cast<const float4*>(ds);
    #pragma unroll 4
    for (int i = 0; i < NPIX / 4; i++) {
        float4 dv = dv4[i];
        float e0 = ex2(fmaf(a2, dv.x, -m2));
        float e1 = ex2(fmaf(a2, dv.y, -m2));
        float e2 = ex2(fmaf(a2, dv.z, -m2));
        float e3 = ex2(fmaf(a2, dv.w, -m2));
        den0 += e0; den1 += e1; den2 += e2; den3 += e3;
        num0 = fmaf(dv.x, e0, num0);
        num1 = fmaf(dv.y, e1, num1);
        num2 = fmaf(dv.z, e2, num2);
        num3 = fmaf(dv.w, e3, num3);
    }
    float S = ((num0 + num1) + (num2 + num3)) / ((den0 + den1) + (den2 + den3));

    // epilogue: 64 coalesced stores
    float* op = out + (size_t)b * OUTC * NPIX + j;
    #pragma unroll
    for (int o = 0; o < OUTC; o++)
        op[o * NPIX] = fmaf(su[o], S, sw0[o]);
}

extern "C" void kernel_launch(void* const* d_in, const int* in_sizes, int n_in,
                              void* d_out, int out_size) {
    const float* seg = (const float*)d_in[0];
    const float* dep = (const float*)d_in[1];
    const float* Wq  = (const float*)d_in[2];
    const float* bq  = (const float*)d_in[3];
    const float* Wk  = (const float*)d_in[4];
    // d_in[5] = bk (provably unused: cancels in softmax)
    const float* Wv  = (const float*)d_in[6];
    const float* bv  = (const float*)d_in[7];
    const float* Wo  = (const float*)d_in[8];
    const float* bo  = (const float*)d_in[9];
    float* out = (float*)d_out;

    setup_kernel<<<1, 64>>>(Wq, bq, Wk, Wv, bv, Wo, bo);
    minmax_kernel<<<NB, 256>>>(dep);
    attn_kernel<<<dim3(NPIX / 128, NB), 128>>>(seg, dep, out);
}

// round 7
// speedup vs baseline: 1.4611x; 1.4611x over previous
#include <cuda_runtime.h>
#include <math_constants.h>

#define NPIX 4096
#define NB   8
#define INC  19
#define OUTC 64
#define TBL  512
#define NXB  32          // NPIX / 128 blocks per batch

// -------- device-global scratch (allowed) --------
__device__ float g_a[NB * NPIX];                 // per-pixel logits a_j
__device__ float g_u[OUTC], g_w0[OUTC];          // folded epilogue weights
__device__ float g_pamin[NB][NXB], g_pamax[NB][NXB];
__device__ float g_pdmin[NB][NXB], g_pdmax[NB][NXB];
__device__ float g_tm[NB][TBL], g_tv[NB][TBL];   // tables: m(a), m'(a)=Var

__device__ __forceinline__ float ex2(float x) {
    float r; asm("ex2.approx.ftz.f32 %0, %1;" : "=f"(r) : "f"(x)); return r;
}
__device__ __forceinline__ float wredmin(float v) {
    #pragma unroll
    for (int o = 16; o; o >>= 1) v = fminf(v, __shfl_xor_sync(0xFFFFFFFFu, v, o));
    return v;
}
__device__ __forceinline__ float wredmax(float v) {
    #pragma unroll
    for (int o = 16; o; o >>= 1) v = fmaxf(v, __shfl_xor_sync(0xFFFFFFFFu, v, o));
    return v;
}
__device__ __forceinline__ float wredsum(float v) {
    #pragma unroll
    for (int o = 16; o; o >>= 1) v += __shfl_xor_sync(0xFFFFFFFFu, v, o);
    return v;
}

// ---------------------------------------------------------------------------
// K1: fold wA/cA per block (redundant, cheap), compute a_j for 128 pixels,
// per-block partial min/max of a and of d (slot-write, no atomics).
// Block (0,0) also folds epilogue weights u, w0.
// grid (NXB, NB), 128 threads.
// ---------------------------------------------------------------------------
__global__ void __launch_bounds__(128)
prep_kernel(const float* __restrict__ seg, const float* __restrict__ d,
            const float* __restrict__ Wq,  const float* __restrict__ bq,
            const float* __restrict__ Wk,  const float* __restrict__ Wv,
            const float* __restrict__ bv,  const float* __restrict__ Wo,
            const float* __restrict__ bo) {
    __shared__ float swA[INC];
    __shared__ float scA;
    __shared__ float rmna[4], rmxa[4], rmnd[4], rmxd[4];

    const int b = blockIdx.y, x = blockIdx.x, tid = threadIdx.x;
    const int w = tid >> 5, l = tid & 31;

    if (tid < INC) {
        float s = 0.f;
        #pragma unroll
        for (int c = 0; c < OUTC; c++) s = fmaf(Wk[c], Wq[c * INC + tid], s);
        swA[tid] = s;
    }
    if (tid == 31) {
        float s = 0.f;
        #pragma unroll
        for (int c = 0; c < OUTC; c++) s = fmaf(Wk[c], bq[c], s);
        scA = s;
    }
    const float dv = d[b * NPIX + x * 128 + tid];
    __syncthreads();

    float a = scA;
    const float* segp = seg + (size_t)b * INC * NPIX + x * 128 + tid;
    #pragma unroll
    for (int ic = 0; ic < INC; ic++) a = fmaf(swA[ic], segp[ic * NPIX], a);
    g_a[b * NPIX + x * 128 + tid] = a;

    float mna = wredmin(a),  mxa = wredmax(a);
    float mnd = wredmin(dv), mxd = wredmax(dv);
    if (l == 0) { rmna[w] = mna; rmxa[w] = mxa; rmnd[w] = mnd; rmxd[w] = mxd; }
    __syncthreads();
    if (tid == 0) {
        float a0 = rmna[0], a1 = rmxa[0], d0 = rmnd[0], d1 = rmxd[0];
        #pragma unroll
        for (int k = 1; k < 4; k++) {
            a0 = fminf(a0, rmna[k]); a1 = fmaxf(a1, rmxa[k]);
            d0 = fminf(d0, rmnd[k]); d1 = fmaxf(d1, rmxd[k]);
        }
        g_pamin[b][x] = a0; g_pamax[b][x] = a1;
        g_pdmin[b][x] = d0; g_pdmax[b][x] = d1;
    }

    if (b == 0 && x == 0 && tid < OUTC) {
        float su = 0.f, sw = 0.f;
        #pragma unroll
        for (int c = 0; c < OUTC; c++) {
            float wo = Wo[tid * OUTC + c];
            su = fmaf(wo, Wv[c], su);
            sw = fmaf(wo, bv[c], sw);
        }
        g_u[tid]  = su;
        g_w0[tid] = sw + bo[tid];
    }
}

// ---------------------------------------------------------------------------
// K2: build per-batch tables. grid (TBL/4, NB), 128 threads (4 warps = 4 nodes).
// Node a_k: m = E_tilt[d], v = Var_tilt[d], via Σe, Σd·e, Σd²·e over smem d, d².
// ---------------------------------------------------------------------------
__global__ void __launch_bounds__(128)
table_kernel(const float* __restrict__ d) {
    __shared__ float ds[NPIX];
    __shared__ float ds2[NPIX];
    __shared__ float sa0, sh, sdmn, sdmx;

    const int b = blockIdx.y, tid = threadIdx.x;
    const int w = tid >> 5, l = tid & 31;

    if (tid == 0) {
        float a0 = CUDART_INF_F, a1 = -CUDART_INF_F;
        float d0 = CUDART_INF_F, d1 = -CUDART_INF_F;
        #pragma unroll 4
        for (int k = 0; k < NXB; k++) {
            a0 = fminf(a0, g_pamin[b][k]); a1 = fmaxf(a1, g_pamax[b][k]);
            d0 = fminf(d0, g_pdmin[b][k]); d1 = fmaxf(d1, g_pdmax[b][k]);
        }
        sa0 = a0;
        sh  = fmaxf(a1 - a0, 1e-12f) * (1.0f / (TBL - 1));
        sdmn = d0; sdmx = d1;
    }
    const float4* dp4 = reinterpret_cast<const float4*>(d + b * NPIX);
    float4* ds4  = reinterpret_cast<float4*>(ds);
    float4* ds24 = reinterpret_cast<float4*>(ds2);
    #pragma unroll
    for (int i = tid; i < NPIX / 4; i += 128) {
        float4 t = dp4[i];
        ds4[i] = t;
        ds24[i] = make_float4(t.x * t.x, t.y * t.y, t.z * t.z, t.w * t.w);
    }
    __syncthreads();

    const int node = blockIdx.x * 4 + w;
    const float LOG2E = 1.4426950408889634f;
    const float a  = sa0 + node * sh;
    const float a2 = a * LOG2E;
    const float m2 = (a2 > 0.f) ? a2 * sdmx : a2 * sdmn;

    float s0 = 0.f, s1 = 0.f, s2 = 0.f;
    const float4* v4  = reinterpret_cast<const float4*>(ds);
    const float4* q4  = reinterpret_cast<const float4*>(ds2);
    #pragma unroll 4
    for (int i = l; i < NPIX / 4; i += 32) {
        float4 dd = v4[i];
        float4 qq = q4[i];
        float e0 = ex2(fmaf(a2, dd.x, -m2));
        float e1 = ex2(fmaf(a2, dd.y, -m2));
        float e2 = ex2(fmaf(a2, dd.z, -m2));
        float e3 = ex2(fmaf(a2, dd.w, -m2));
        s0 += e0 + e1 + e2 + e3;
        s1 = fmaf(dd.x, e0, s1); s1 = fmaf(dd.y, e1, s1);
        s1 = fmaf(dd.z, e2, s1); s1 = fmaf(dd.w, e3, s1);
        s2 = fmaf(qq.x, e0, s2); s2 = fmaf(qq.y, e1, s2);
        s2 = fmaf(qq.z, e2, s2); s2 = fmaf(qq.w, e3, s2);
    }
    s0 = wredsum(s0); s1 = wredsum(s1); s2 = wredsum(s2);
    if (l == 0) {
        float inv = 1.0f / s0;
        float m = s1 * inv;
        float v = fmaxf(fmaf(s2, inv, -m * m), 0.f);
        g_tm[b][node] = m;
        g_tv[b][node] = v;
    }
}

// ---------------------------------------------------------------------------
// K3: per-pixel cubic Hermite interpolation S(a_j) + epilogue.
// grid (NXB, NB), 128 threads.
// ---------------------------------------------------------------------------
__global__ void __launch_bounds__(128)
final_kernel(float* __restrict__ out) {
    __shared__ float stm[TBL], stv[TBL];
    __shared__ float ssu[OUTC], ssw[OUTC];
    __shared__ float sa0, sh, sinvh;

    const int b = blockIdx.y, x = blockIdx.x, tid = threadIdx.x;

    #pragma unroll
    for (int i = tid; i < TBL; i += 128) { stm[i] = g_tm[b][i]; stv[i] = g_tv[b][i]; }
    if (tid < OUTC) { ssu[tid] = g_u[tid]; ssw[tid] = g_w0[tid]; }
    if (tid == 0) {
        float a0 = CUDART_INF_F, a1 = -CUDART_INF_F;
        #pragma unroll 4
        for (int k = 0; k < NXB; k++) {
            a0 = fminf(a0, g_pamin[b][k]); a1 = fmaxf(a1, g_pamax[b][k]);
        }
        float h = fmaxf(a1 - a0, 1e-12f) * (1.0f / (TBL - 1));
        sa0 = a0; sh = h; sinvh = 1.0f / h;
    }
    __syncthreads();

    const float a = g_a[b * NPIX + x * 128 + tid];
    float t = fmaxf((a - sa0) * sinvh, 0.f);
    int   k = min((int)t, TBL - 2);
    float u = t - (float)k;

    float m0 = stm[k], m1 = stm[k + 1];
    float v0 = stv[k], v1 = stv[k + 1];
    float u2   = u * u;
    float um1  = u - 1.f;
    float um12 = um1 * um1;
    float h00 = fmaf(2.f, u, 1.f) * um12;
    float h10 = u * um12;
    float h01 = u2 * fmaf(-2.f, u, 3.f);
    float h11 = u2 * um1;
    float S = fmaf(h00, m0, fmaf(h01, m1, sh * fmaf(h10, v0, h11 * v1)));

    float* op = out + (size_t)b * OUTC * NPIX + x * 128 + tid;
    #pragma unroll
    for (int o = 0; o < OUTC; o++)
        op[o * NPIX] = fmaf(ssu[o], S, ssw[o]);
}

extern "C" void kernel_launch(void* const* d_in, const int* in_sizes, int n_in,
                              void* d_out, int out_size) {
    const float* seg = (const float*)d_in[0];
    const float* dep = (const float*)d_in[1];
    const float* Wq  = (const float*)d_in[2];
    const float* bq  = (const float*)d_in[3];
    const float* Wk  = (const float*)d_in[4];
    // d_in[5] = bk: cancels exactly in the row softmax
    const float* Wv  = (const float*)d_in[6];
    const float* bv  = (const float*)d_in[7];
    const float* Wo  = (const float*)d_in[8];
    const float* bo  = (const float*)d_in[9];
    float* out = (float*)d_out;

    prep_kernel<<<dim3(NXB, NB), 128>>>(seg, dep, Wq, bq, Wk, Wv, bv, Wo, bo);
    table_kernel<<<dim3(TBL / 4, NB), 128>>>(dep);
    final_kernel<<<dim3(NXB, NB), 128>>>(out);
}